// round 10
// baseline (speedup 1.0000x reference)
#include <cuda_runtime.h>
#include <math.h>

#define SLEN 4096
#define EDIM 256
#define HDIM 256
#define TAGS 32
#define NEGV (-10000.0f)
#define CL 8            // CTAs per cluster (one cluster per direction)
#define STARTTAG 30
#define STOPTAG  31

// ---------------- scratch (device globals; no allocation allowed) ----------------
__device__ float g_xg[2][SLEN][4 * HDIM];           // 32 MB : precomputed input gates
__device__ __align__(16) float g_hs[2][SLEN][HDIM]; // 8 MB  : hidden states
__device__ float g_feats[SLEN][TAGS];               // 512 KB

// packed fp32x2 FMA (Blackwell FFMA2): d = a*b + c elementwise on float2
__device__ __forceinline__ float2 ffma2(float2 a, float2 b, float2 c) {
    float2 d;
    asm("fma.rn.f32x2 %0, %1, %2, %3;"
        : "=l"(*reinterpret_cast<unsigned long long*>(&d))
        : "l"(*reinterpret_cast<unsigned long long*>(&a)),
          "l"(*reinterpret_cast<unsigned long long*>(&b)),
          "l"(*reinterpret_cast<unsigned long long*>(&c)));
    return d;
}

// fast tanh via MUFU (used on the c-state path)
__device__ __forceinline__ float fast_tanh(float x) {
    float e = __expf(-2.0f * x);
    return __fdividef(1.0f - e, 1.0f + e);
}

// ---------------- K1: xg[d][t][r] = emb[sent_d(t)] . w_ih_d[r] + b_d[r] ----------
__global__ void k1_xg(const int* __restrict__ sent,
                      const float* __restrict__ embedding,
                      const float* __restrict__ w_ih_f, const float* __restrict__ b_f,
                      const float* __restrict__ w_ih_b, const float* __restrict__ b_b)
{
    __shared__ __align__(16) float embs[16][EDIM];
    const int d  = blockIdx.z;
    const int t0 = blockIdx.x * 16;
    const int n  = blockIdx.y * 256 + threadIdx.x;   // gate row 0..1023

    for (int tt = 0; tt < 16; tt++) {
        int pos  = t0 + tt;
        int spos = d ? (SLEN - 1 - pos) : pos;
        int tok  = sent[spos];
        embs[tt][threadIdx.x] = embedding[(size_t)tok * EDIM + threadIdx.x];
    }
    __syncthreads();

    const float* W = d ? w_ih_b : w_ih_f;
    const float* B = d ? b_b    : b_f;
    float2 acc[16];
    float bias = B[n];
#pragma unroll
    for (int tt = 0; tt < 16; tt++) acc[tt] = make_float2(bias, 0.0f);

    const float4* Wr = (const float4*)(W + (size_t)n * EDIM);
#pragma unroll 4
    for (int e4 = 0; e4 < EDIM / 4; e4++) {
        float4 w4 = __ldg(&Wr[e4]);
        float2 wA = make_float2(w4.x, w4.y);
        float2 wB = make_float2(w4.z, w4.w);
#pragma unroll
        for (int tt = 0; tt < 16; tt++) {
            float4 ev = *(const float4*)&embs[tt][e4 * 4];
            acc[tt] = ffma2(wA, make_float2(ev.x, ev.y), acc[tt]);
            acc[tt] = ffma2(wB, make_float2(ev.z, ev.w), acc[tt]);
        }
    }
#pragma unroll
    for (int tt = 0; tt < 16; tt++) g_xg[d][t0 + tt][n] = acc[tt].x + acc[tt].y;
}

// ---------------- K2: clustered bidirectional LSTM recurrence --------------------
// Grid = 16 CTAs = 2 clusters of 8 (one per direction), 256 thr/CTA.
// CTA rank owns j in [rank*32, rank*32+32). Warp w owns jl in [4w, 4w+4).
// Handshake: ZERO ordering ops; one st.async.v4.b32 per warp per target CTA
// carries mbarrier::complete_tx. Two alternating mbarriers, 4-deep h ring.
// xg is consumed through a 2-step register prefetch pipeline: load latency
// has >= 2 full steps of slack and never touches the critical path.
__global__ void __launch_bounds__(256, 1) __cluster_dims__(CL, 1, 1)
k2_lstm(const float* __restrict__ h0, const float* __restrict__ c0,
        const float* __restrict__ w_hh_f, const float* __restrict__ w_hh_b)
{
    __shared__ __align__(16) float hbuf[4][HDIM];   // 4-deep h ring, filled via st.async
    __shared__ __align__(8) unsigned long long mbar[2];

    const int d = blockIdx.x >> 3;                  // cluster id = direction
    unsigned crank;
    asm("mov.u32 %0, %%cluster_ctarank;" : "=r"(crank));
    const int tid  = threadIdx.x;
    const int w    = tid >> 5;
    const int l    = tid & 31;
    const int a    = l >> 3;                        // j slot within warp
    const int gate = (l >> 1) & 3;                  // i,f,g,o
    const int half = l & 1;                         // column half (interleaved)
    const int jl   = w * 4 + a;                     // 0..31
    const int j    = (int)crank * 32 + jl;          // global h index
    const int j0   = (int)crank * 32 + w * 4;       // warp's first j
    const int grow = gate * HDIM + j;               // gate row in [0,1024)

    const float* W = d ? w_hh_b : w_hh_f;
    float4 wr[32];                                  // 128 weights / thread
#pragma unroll
    for (int m = 0; m < 32; m++)
        wr[m] = *(const float4*)(W + (size_t)grow * HDIM + (size_t)(m * 2 + half) * 4);

    unsigned hb = (unsigned)__cvta_generic_to_shared(&hbuf[0][0]);
    unsigned mb = (unsigned)__cvta_generic_to_shared(&mbar[0]);
    unsigned rh[CL], rm[CL];
#pragma unroll
    for (int c = 0; c < CL; c++) {
        asm("mapa.shared::cluster.u32 %0, %1, %2;" : "=r"(rh[c]) : "r"(hb), "r"(c));
        asm("mapa.shared::cluster.u32 %0, %1, %2;" : "=r"(rm[c]) : "r"(mb), "r"(c));
    }

    if (tid == 0) {
        asm volatile("mbarrier.init.shared.b64 [%0], %1;" :: "r"(mb),     "r"(1) : "memory");
        asm volatile("mbarrier.init.shared.b64 [%0], %1;" :: "r"(mb + 8), "r"(1) : "memory");
        // pre-post: h_1 arrives on mbar[1], h_2 on mbar[0]; 1024 B each
        asm volatile("mbarrier.arrive.expect_tx.shared.b64 _, [%0], %1;"
                     :: "r"(mb + 8), "r"(HDIM * 4) : "memory");
        asm volatile("mbarrier.arrive.expect_tx.shared.b64 _, [%0], %1;"
                     :: "r"(mb),     "r"(HDIM * 4) : "memory");
    }
    hbuf[0][tid] = h0[d * HDIM + tid];              // step 1 reads hbuf[0] = h0
    __syncthreads();
    // all CTAs' mbarrier init done before any st.async can target them
    asm volatile("barrier.cluster.arrive.aligned;" ::: "memory");
    asm volatile("barrier.cluster.wait.aligned;"   ::: "memory");

    const bool prod = ((l & 7) == 0);               // lanes 0,8,16,24: own a j
    float cst = c0[d * HDIM + j];                   // used only on prod lanes

    // 2-step xg prefetch pipeline
    float xw_cur = __ldg(&g_xg[d][0][grow]);
    float xw_nxt = __ldg(&g_xg[d][1][grow]);

    for (int s = 1; s <= SLEN; s++) {
        const int t = s - 1;
        const float xw = xw_cur;                    // loaded >= 2 steps ago
        xw_cur = xw_nxt;
        {
            int tpf = (s + 1 < SLEN) ? (s + 1) : (SLEN - 1);
            xw_nxt = __ldg(&g_xg[d][tpf][grow]);    // for step s+2; issued pre-wait
        }

        if (s > 1) {                                // wait h_{s-1} on mbar[(s-1)&1]
            unsigned mbw = mb + (unsigned)((s - 1) & 1) * 8u;
            unsigned par = (unsigned)(((s - 2) >> 1) & 1);
            unsigned done;
            asm volatile(
                "{\n\t.reg .pred p;\n\t"
                "mbarrier.try_wait.parity.acquire.cluster.shared::cta.b64 p, [%1], %2, 0x989680;\n\t"
                "selp.b32 %0, 1, 0, p;\n\t}"
                : "=r"(done) : "r"(mbw), "r"(par) : "memory");
            while (!done) {
                asm volatile(
                    "{\n\t.reg .pred p;\n\t"
                    "mbarrier.try_wait.parity.acquire.cluster.shared::cta.b64 p, [%1], %2, 0x989680;\n\t"
                    "selp.b32 %0, 1, 0, p;\n\t}"
                    : "=r"(done) : "r"(mbw), "r"(par) : "memory");
            }
            // this barrier's next phase handles h_{s+1}: re-arm it now
            if (tid == 0 && s + 1 <= SLEN)
                asm volatile("mbarrier.arrive.expect_tx.shared.b64 _, [%0], %1;"
                             :: "r"(mbw), "r"(HDIM * 4) : "memory");
        }

        const float* hsm = &hbuf[(s - 1) & 3][0];
        float2 acc[4];
#pragma unroll
        for (int k = 0; k < 4; k++) acc[k] = make_float2(0.0f, 0.0f);
#pragma unroll
        for (int m = 0; m < 32; m++) {
            float4 h4 = *(const float4*)(hsm + (m * 2 + half) * 4);
            float4 w4 = wr[m];
            float2 ac = acc[m & 3];
            ac = ffma2(make_float2(w4.x, w4.y), make_float2(h4.x, h4.y), ac);
            ac = ffma2(make_float2(w4.z, w4.w), make_float2(h4.z, h4.w), ac);
            acc[m & 3] = ac;
        }
        float accS = ((acc[0].x + acc[0].y) + (acc[1].x + acc[1].y))
                   + ((acc[2].x + acc[2].y) + (acc[3].x + acc[3].y));
        accS += __shfl_xor_sync(0xffffffffu, accS, 1);   // combine halves

        // unified activation: ONE exp + ONE div for every lane.
        // sigmoid(x) = 1/(1+e^-x); tanh(x) = 2/(1+e^-2x) - 1 = (1-e^-2x)/(1+e^-2x)
        const bool isg = (gate == 2);
        float av  = accS + xw;
        float xs  = isg ? (av + av) : av;
        float e   = __expf(-xs);
        float r   = __fdividef(1.0f, 1.0f + e);
        float val = isg ? fmaf(2.0f, r, -1.0f) : r;

        const int base = l & 24;                    // lane group of this j
        float iv = __shfl_sync(0xffffffffu, val, base + 0);
        float fv = __shfl_sync(0xffffffffu, val, base + 2);
        float gv = __shfl_sync(0xffffffffu, val, base + 4);
        float ov = __shfl_sync(0xffffffffu, val, base + 6);

        float hv = 0.0f;
        if (prod) {
            cst = fmaf(fv, cst, iv * gv);
            hv  = ov * fast_tanh(cst);
        }
        // gather warp's 4 h-values to all lanes; lanes 0..7 send to CTA c = l
        float h0v = __shfl_sync(0xffffffffu, hv, 0);
        float h1v = __shfl_sync(0xffffffffu, hv, 8);
        float h2v = __shfl_sync(0xffffffffu, hv, 16);
        float h3v = __shfl_sync(0xffffffffu, hv, 24);

        if (l < CL) {
            unsigned dst  = rh[l] + (unsigned)(((s & 3) * HDIM + j0) * 4);
            unsigned mdst = rm[l] + (unsigned)((s & 1) * 8);
            asm volatile(
                "st.async.weak.shared::cluster.mbarrier::complete_tx::bytes.v4.b32 "
                "[%0], {%1, %2, %3, %4}, [%5];"
                :: "r"(dst),
                   "r"(__float_as_uint(h0v)), "r"(__float_as_uint(h1v)),
                   "r"(__float_as_uint(h2v)), "r"(__float_as_uint(h3v)),
                   "r"(mdst) : "memory");
        }
        if (l == 0)
            __stcg((float4*)&g_hs[d][t][j0], make_float4(h0v, h1v, h2v, h3v));
    }

    // no CTA may exit while peers still write into its SMEM
    asm volatile("barrier.cluster.arrive.aligned;" ::: "memory");
    asm volatile("barrier.cluster.wait.aligned;"   ::: "memory");
}

// ---------------- K3: feats[t] = [hs_f[t], hs_b[S-1-t]] @ lin_w^T + lin_b --------
__global__ void k3_feats(const float* __restrict__ lin_w, const float* __restrict__ lin_b)
{
    __shared__ __align__(16) float cat[2 * HDIM];
    const int t   = blockIdx.x;
    const int tid = threadIdx.x;                // 256
    cat[tid]        = g_hs[0][t][tid];
    cat[HDIM + tid] = g_hs[1][SLEN - 1 - t][tid];
    __syncthreads();

    const int n = tid >> 3, seg = tid & 7;
    const float* w  = lin_w + (size_t)n * 2 * HDIM + seg * 64;
    const float* cc = cat + seg * 64;
    float s = 0.0f;
#pragma unroll 16
    for (int k = 0; k < 64; k++) s = fmaf(w[k], cc[k], s);
    s += __shfl_xor_sync(0xffffffffu, s, 1);
    s += __shfl_xor_sync(0xffffffffu, s, 2);
    s += __shfl_xor_sync(0xffffffffu, s, 4);
    if (seg == 0) g_feats[t][n] = s + lin_b[n];
}

// ---------------- K4: single-warp Viterbi + backtrack (bps in SMEM) --------------
__global__ void __launch_bounds__(32, 1) k4_viterbi(
    const float* __restrict__ trans, float* __restrict__ out, int out_size)
{
    extern __shared__ unsigned char bps[];      // SLEN*TAGS bytes = 128 KB
    const int lane = threadIdx.x;

    float trn[TAGS];
#pragma unroll
    for (int p = 0; p < TAGS; p++) trn[p] = __ldg(&trans[lane * TAGS + p]);
    const float stop_tr = __ldg(&trans[STOPTAG * TAGS + lane]);

    float fv  = (lane == STARTTAG) ? 0.0f : NEGV;
    float ftc = g_feats[0][lane];
    float ftn = g_feats[1][lane];

    for (int t = 0; t < SLEN; t++) {
        float v[TAGS];
        int   bi[TAGS];
#pragma unroll
        for (int p = 0; p < TAGS; p++) {
            v[p]  = __shfl_sync(0xffffffffu, fv, p) + trn[p];
            bi[p] = p;
        }
        // first-max tree: strict > keeps the lower index on ties (== jnp.argmax)
#pragma unroll
        for (int s = 1; s < TAGS; s <<= 1) {
#pragma unroll
            for (int k = 0; k < TAGS; k += 2 * s) {
                if (v[k + s] > v[k]) { v[k] = v[k + s]; bi[k] = bi[k + s]; }
            }
        }
        bps[t * TAGS + lane] = (unsigned char)bi[0];
        fv  = v[0] + ftc;
        ftc = ftn;
        ftn = (t + 2 < SLEN) ? g_feats[t + 2][lane] : 0.0f;
    }

    float v = fv + stop_tr;
    int   b = lane;
#pragma unroll
    for (int ofs = 16; ofs > 0; ofs >>= 1) {
        float ov = __shfl_down_sync(0xffffffffu, v, ofs);
        int   oi = __shfl_down_sync(0xffffffffu, b, ofs);
        if (ov > v || (ov == v && oi < b)) { v = ov; b = oi; }
    }

    if (lane == 0) {
        const int off = (out_size > SLEN) ? 1 : 0;
        if (off) out[0] = v;
        int cur = b;
        for (int t = SLEN - 1; t >= 0; t--) {
            int idx = off + t;
            if (idx < out_size) out[idx] = (float)cur;
            cur = bps[t * TAGS + cur];
        }
    }
}

// ---------------- launch ----------------------------------------------------------
extern "C" void kernel_launch(void* const* d_in, const int* in_sizes, int n_in,
                              void* d_out, int out_size)
{
    (void)in_sizes; (void)n_in;
    const int*   sent      = (const int*)  d_in[0];
    const float* h0        = (const float*)d_in[1];
    const float* c0        = (const float*)d_in[2];
    const float* embedding = (const float*)d_in[3];
    const float* w_ih_f    = (const float*)d_in[4];
    const float* w_hh_f    = (const float*)d_in[5];
    const float* b_f       = (const float*)d_in[6];
    const float* w_ih_b    = (const float*)d_in[7];
    const float* w_hh_b    = (const float*)d_in[8];
    const float* b_b       = (const float*)d_in[9];
    const float* lin_w     = (const float*)d_in[10];
    const float* lin_b     = (const float*)d_in[11];
    const float* trans     = (const float*)d_in[12];

    dim3 g1(SLEN / 16, 4, 2);
    k1_xg<<<g1, 256>>>(sent, embedding, w_ih_f, b_f, w_ih_b, b_b);
    k2_lstm<<<2 * CL, 256>>>(h0, c0, w_hh_f, w_hh_b);
    k3_feats<<<SLEN, 256>>>(lin_w, lin_b);

    cudaFuncSetAttribute(k4_viterbi, cudaFuncAttributeMaxDynamicSharedMemorySize,
                         SLEN * TAGS);
    k4_viterbi<<<1, 32, SLEN * TAGS>>>(trans, (float*)d_out, out_size);
}

// round 11
// speedup vs baseline: 1.0921x; 1.0921x over previous
#include <cuda_runtime.h>
#include <math.h>

#define SLEN 4096
#define EDIM 256
#define HDIM 256
#define TAGS 32
#define NEGV (-10000.0f)
#define CL 8            // CTAs per cluster (one cluster per direction)
#define STARTTAG 30
#define STOPTAG  31

// ---------------- scratch (device globals; no allocation allowed) ----------------
__device__ float g_xg[2][SLEN][4 * HDIM];           // 32 MB : precomputed input gates
__device__ __align__(16) float g_hs[2][SLEN][HDIM]; // 8 MB  : hidden states
__device__ float g_feats[SLEN][TAGS];               // 512 KB

// packed fp32x2 FMA (Blackwell FFMA2): d = a*b + c elementwise on float2
__device__ __forceinline__ float2 ffma2(float2 a, float2 b, float2 c) {
    float2 d;
    asm("fma.rn.f32x2 %0, %1, %2, %3;"
        : "=l"(*reinterpret_cast<unsigned long long*>(&d))
        : "l"(*reinterpret_cast<unsigned long long*>(&a)),
          "l"(*reinterpret_cast<unsigned long long*>(&b)),
          "l"(*reinterpret_cast<unsigned long long*>(&c)));
    return d;
}

// fast sigmoid/tanh via MUFU (__expf rel err ~1e-7: safe for argmax margins)
__device__ __forceinline__ float fast_sigmoid(float x) {
    float e = __expf(-x);
    return __fdividef(1.0f, 1.0f + e);
}
__device__ __forceinline__ float fast_tanh(float x) {
    float e = __expf(-2.0f * x);
    return __fdividef(1.0f - e, 1.0f + e);
}

// ---------------- K1: xg[d][t][r] = emb[sent_d(t)] . w_ih_d[r] + b_d[r] ----------
__global__ void k1_xg(const int* __restrict__ sent,
                      const float* __restrict__ embedding,
                      const float* __restrict__ w_ih_f, const float* __restrict__ b_f,
                      const float* __restrict__ w_ih_b, const float* __restrict__ b_b)
{
    __shared__ __align__(16) float embs[16][EDIM];
    const int d  = blockIdx.z;
    const int t0 = blockIdx.x * 16;
    const int n  = blockIdx.y * 256 + threadIdx.x;   // gate row 0..1023

    for (int tt = 0; tt < 16; tt++) {
        int pos  = t0 + tt;
        int spos = d ? (SLEN - 1 - pos) : pos;
        int tok  = sent[spos];
        embs[tt][threadIdx.x] = embedding[(size_t)tok * EDIM + threadIdx.x];
    }
    __syncthreads();

    const float* W = d ? w_ih_b : w_ih_f;
    const float* B = d ? b_b    : b_f;
    float2 acc[16];
    float bias = B[n];
#pragma unroll
    for (int tt = 0; tt < 16; tt++) acc[tt] = make_float2(bias, 0.0f);

    const float4* Wr = (const float4*)(W + (size_t)n * EDIM);
#pragma unroll 4
    for (int e4 = 0; e4 < EDIM / 4; e4++) {
        float4 w4 = __ldg(&Wr[e4]);
        float2 wA = make_float2(w4.x, w4.y);
        float2 wB = make_float2(w4.z, w4.w);
#pragma unroll
        for (int tt = 0; tt < 16; tt++) {
            float4 ev = *(const float4*)&embs[tt][e4 * 4];
            acc[tt] = ffma2(wA, make_float2(ev.x, ev.y), acc[tt]);
            acc[tt] = ffma2(wB, make_float2(ev.z, ev.w), acc[tt]);
        }
    }
#pragma unroll
    for (int tt = 0; tt < 16; tt++) g_xg[d][t0 + tt][n] = acc[tt].x + acc[tt].y;
}

// ---------------- K2: clustered bidirectional LSTM recurrence --------------------
// Grid = 16 CTAs = 2 clusters of 8 (one per direction), 256 thr/CTA.
// CTA rank owns j in [rank*32, rank*32+32). Warp w owns jl in [4w, 4w+4).
// Handshake: ZERO ordering ops; one st.async.v4.b32 per warp per target CTA
// carries mbarrier::complete_tx. Two alternating mbarriers, 4-deep h ring.
// Per-lane remote addresses are SCALARS (computed once via mapa for c = l&7);
// no dynamically-indexed arrays -> no local-memory traffic on the hot path.
__global__ void __launch_bounds__(256, 1) __cluster_dims__(CL, 1, 1)
k2_lstm(const float* __restrict__ h0, const float* __restrict__ c0,
        const float* __restrict__ w_hh_f, const float* __restrict__ w_hh_b)
{
    __shared__ __align__(16) float hbuf[4][HDIM];   // 4-deep h ring, filled via st.async
    __shared__ __align__(8) unsigned long long mbar[2];

    const int d = blockIdx.x >> 3;                  // cluster id = direction
    unsigned crank;
    asm("mov.u32 %0, %%cluster_ctarank;" : "=r"(crank));
    const int tid  = threadIdx.x;
    const int w    = tid >> 5;
    const int l    = tid & 31;
    const int a    = l >> 3;                        // j slot within warp
    const int gate = (l >> 1) & 3;                  // i,f,g,o
    const int half = l & 1;                         // column half (interleaved)
    const int jl   = w * 4 + a;                     // 0..31
    const int j    = (int)crank * 32 + jl;          // global h index
    const int j0   = (int)crank * 32 + w * 4;       // warp's first j
    const int grow = gate * HDIM + j;               // gate row in [0,1024)

    const float* W = d ? w_hh_b : w_hh_f;
    float4 wr[32];                                  // 128 weights / thread
#pragma unroll
    for (int m = 0; m < 32; m++)
        wr[m] = *(const float4*)(W + (size_t)grow * HDIM + (size_t)(m * 2 + half) * 4);

    unsigned hb = (unsigned)__cvta_generic_to_shared(&hbuf[0][0]);
    unsigned mb = (unsigned)__cvta_generic_to_shared(&mbar[0]);
    // per-lane scalar remote addresses: this lane's send target is CTA (l & 7)
    unsigned r_h, r_m;
    {
        unsigned myc = (unsigned)(l & 7);
        asm("mapa.shared::cluster.u32 %0, %1, %2;" : "=r"(r_h) : "r"(hb), "r"(myc));
        asm("mapa.shared::cluster.u32 %0, %1, %2;" : "=r"(r_m) : "r"(mb), "r"(myc));
    }

    if (tid == 0) {
        asm volatile("mbarrier.init.shared.b64 [%0], %1;" :: "r"(mb),     "r"(1) : "memory");
        asm volatile("mbarrier.init.shared.b64 [%0], %1;" :: "r"(mb + 8), "r"(1) : "memory");
        // pre-post: h_1 arrives on mbar[1], h_2 on mbar[0]; 1024 B each
        asm volatile("mbarrier.arrive.expect_tx.shared.b64 _, [%0], %1;"
                     :: "r"(mb + 8), "r"(HDIM * 4) : "memory");
        asm volatile("mbarrier.arrive.expect_tx.shared.b64 _, [%0], %1;"
                     :: "r"(mb),     "r"(HDIM * 4) : "memory");
    }
    hbuf[0][tid] = h0[d * HDIM + tid];              // step 1 reads hbuf[0] = h0
    __syncthreads();
    // all CTAs' mbarrier init done before any st.async can target them
    asm volatile("barrier.cluster.arrive.aligned;" ::: "memory");
    asm volatile("barrier.cluster.wait.aligned;"   ::: "memory");

    const bool prod = ((l & 7) == 0);               // lanes 0,8,16,24: own a j
    float cst = c0[d * HDIM + j];                   // used only on prod lanes

    for (int s = 1; s <= SLEN; s++) {
        const int t = s - 1;
        // xg prefetch: issued before the wait, overlaps the mbarrier sleep
        float xw = __ldg(&g_xg[d][t][grow]);

        if (s > 1) {                                // wait h_{s-1} on mbar[(s-1)&1]
            unsigned mbw = mb + (unsigned)((s - 1) & 1) * 8u;
            unsigned par = (unsigned)(((s - 2) >> 1) & 1);
            unsigned done;
            asm volatile(
                "{\n\t.reg .pred p;\n\t"
                "mbarrier.try_wait.parity.acquire.cluster.shared::cta.b64 p, [%1], %2, 0x989680;\n\t"
                "selp.b32 %0, 1, 0, p;\n\t}"
                : "=r"(done) : "r"(mbw), "r"(par) : "memory");
            while (!done) {
                asm volatile(
                    "{\n\t.reg .pred p;\n\t"
                    "mbarrier.try_wait.parity.acquire.cluster.shared::cta.b64 p, [%1], %2, 0x989680;\n\t"
                    "selp.b32 %0, 1, 0, p;\n\t}"
                    : "=r"(done) : "r"(mbw), "r"(par) : "memory");
            }
            // this barrier's next phase handles h_{s+1}: re-arm it now
            if (tid == 0 && s + 1 <= SLEN)
                asm volatile("mbarrier.arrive.expect_tx.shared.b64 _, [%0], %1;"
                             :: "r"(mbw), "r"(HDIM * 4) : "memory");
        }

        const float* hsm = &hbuf[(s - 1) & 3][0];
        float2 acc[4];
#pragma unroll
        for (int k = 0; k < 4; k++) acc[k] = make_float2(0.0f, 0.0f);
#pragma unroll
        for (int m = 0; m < 32; m++) {
            float4 h4 = *(const float4*)(hsm + (m * 2 + half) * 4);
            float4 w4 = wr[m];
            float2 ac = acc[m & 3];
            ac = ffma2(make_float2(w4.x, w4.y), make_float2(h4.x, h4.y), ac);
            ac = ffma2(make_float2(w4.z, w4.w), make_float2(h4.z, h4.w), ac);
            acc[m & 3] = ac;
        }
        float accS = ((acc[0].x + acc[0].y) + (acc[1].x + acc[1].y))
                   + ((acc[2].x + acc[2].y) + (acc[3].x + acc[3].y));
        accS += __shfl_xor_sync(0xffffffffu, accS, 1);   // combine halves

        float av  = accS + xw;
        float val = (gate == 2) ? fast_tanh(av) : fast_sigmoid(av);

        const int base = l & 24;                    // lane group of this j
        float iv = __shfl_sync(0xffffffffu, val, base + 0);
        float fv = __shfl_sync(0xffffffffu, val, base + 2);
        float gv = __shfl_sync(0xffffffffu, val, base + 4);
        float ov = __shfl_sync(0xffffffffu, val, base + 6);

        float hv = 0.0f;
        if (prod) {
            cst = fmaf(fv, cst, iv * gv);
            hv  = ov * fast_tanh(cst);
        }
        // gather warp's 4 h-values to all lanes; lanes 0..7 send to CTA c = l
        float h0v = __shfl_sync(0xffffffffu, hv, 0);
        float h1v = __shfl_sync(0xffffffffu, hv, 8);
        float h2v = __shfl_sync(0xffffffffu, hv, 16);
        float h3v = __shfl_sync(0xffffffffu, hv, 24);

        if (l < CL) {
            unsigned dst  = r_h + (unsigned)(((s & 3) * HDIM + j0) * 4);
            unsigned mdst = r_m + (unsigned)((s & 1) * 8);
            asm volatile(
                "st.async.weak.shared::cluster.mbarrier::complete_tx::bytes.v4.b32 "
                "[%0], {%1, %2, %3, %4}, [%5];"
                :: "r"(dst),
                   "r"(__float_as_uint(h0v)), "r"(__float_as_uint(h1v)),
                   "r"(__float_as_uint(h2v)), "r"(__float_as_uint(h3v)),
                   "r"(mdst) : "memory");
        }
        if (l == 0)
            __stcg((float4*)&g_hs[d][t][j0], make_float4(h0v, h1v, h2v, h3v));
    }

    // no CTA may exit while peers still write into its SMEM
    asm volatile("barrier.cluster.arrive.aligned;" ::: "memory");
    asm volatile("barrier.cluster.wait.aligned;"   ::: "memory");
}

// ---------------- K3: feats[t] = [hs_f[t], hs_b[S-1-t]] @ lin_w^T + lin_b --------
__global__ void k3_feats(const float* __restrict__ lin_w, const float* __restrict__ lin_b)
{
    __shared__ __align__(16) float cat[2 * HDIM];
    const int t   = blockIdx.x;
    const int tid = threadIdx.x;                // 256
    cat[tid]        = g_hs[0][t][tid];
    cat[HDIM + tid] = g_hs[1][SLEN - 1 - t][tid];
    __syncthreads();

    const int n = tid >> 3, seg = tid & 7;
    const float* w  = lin_w + (size_t)n * 2 * HDIM + seg * 64;
    const float* cc = cat + seg * 64;
    float s = 0.0f;
#pragma unroll 16
    for (int k = 0; k < 64; k++) s = fmaf(w[k], cc[k], s);
    s += __shfl_xor_sync(0xffffffffu, s, 1);
    s += __shfl_xor_sync(0xffffffffu, s, 2);
    s += __shfl_xor_sync(0xffffffffu, s, 4);
    if (seg == 0) g_feats[t][n] = s + lin_b[n];
}

// ---------------- K4: single-warp Viterbi + backtrack (bps in SMEM) --------------
// fv is exchanged through a double-buffered SMEM row (1 STS + 1 syncwarp +
// 8 broadcast LDS.128) instead of 32 SHFLs. Arithmetic order identical.
__global__ void __launch_bounds__(32, 1) k4_viterbi(
    const float* __restrict__ trans, float* __restrict__ out, int out_size)
{
    extern __shared__ unsigned char bps[];      // SLEN*TAGS bytes = 128 KB
    __shared__ __align__(16) float fv_s[2][TAGS];
    const int lane = threadIdx.x;

    float trn[TAGS];
#pragma unroll
    for (int p = 0; p < TAGS; p++) trn[p] = __ldg(&trans[lane * TAGS + p]);
    const float stop_tr = __ldg(&trans[STOPTAG * TAGS + lane]);

    float fv  = (lane == STARTTAG) ? 0.0f : NEGV;
    fv_s[0][lane] = fv;
    __syncwarp();
    float ftc = g_feats[0][lane];
    float ftn = g_feats[1][lane];

    for (int t = 0; t < SLEN; t++) {
        // read the full fv row via broadcast LDS.128
        float fvv[TAGS];
#pragma unroll
        for (int q = 0; q < TAGS / 4; q++) {
            float4 f4 = *(const float4*)&fv_s[t & 1][q * 4];
            fvv[q * 4 + 0] = f4.x; fvv[q * 4 + 1] = f4.y;
            fvv[q * 4 + 2] = f4.z; fvv[q * 4 + 3] = f4.w;
        }
        float v[TAGS];
        int   bi[TAGS];
#pragma unroll
        for (int p = 0; p < TAGS; p++) {
            v[p]  = fvv[p] + trn[p];
            bi[p] = p;
        }
        // first-max tree: strict > keeps the lower index on ties (== jnp.argmax)
#pragma unroll
        for (int s = 1; s < TAGS; s <<= 1) {
#pragma unroll
            for (int k = 0; k < TAGS; k += 2 * s) {
                if (v[k + s] > v[k]) { v[k] = v[k + s]; bi[k] = bi[k + s]; }
            }
        }
        bps[t * TAGS + lane] = (unsigned char)bi[0];
        fv  = v[0] + ftc;
        fv_s[(t + 1) & 1][lane] = fv;
        ftc = ftn;
        ftn = (t + 2 < SLEN) ? g_feats[t + 2][lane] : 0.0f;
        __syncwarp();                            // fv row visible before next read
    }

    float v = fv + stop_tr;
    int   b = lane;
#pragma unroll
    for (int ofs = 16; ofs > 0; ofs >>= 1) {
        float ov = __shfl_down_sync(0xffffffffu, v, ofs);
        int   oi = __shfl_down_sync(0xffffffffu, b, ofs);
        if (ov > v || (ov == v && oi < b)) { v = ov; b = oi; }
    }

    if (lane == 0) {
        const int off = (out_size > SLEN) ? 1 : 0;
        if (off) out[0] = v;
        int cur = b;
        for (int t = SLEN - 1; t >= 0; t--) {
            int idx = off + t;
            if (idx < out_size) out[idx] = (float)cur;
            cur = bps[t * TAGS + cur];
        }
    }
}

// ---------------- launch ----------------------------------------------------------
extern "C" void kernel_launch(void* const* d_in, const int* in_sizes, int n_in,
                              void* d_out, int out_size)
{
    (void)in_sizes; (void)n_in;
    const int*   sent      = (const int*)  d_in[0];
    const float* h0        = (const float*)d_in[1];
    const float* c0        = (const float*)d_in[2];
    const float* embedding = (const float*)d_in[3];
    const float* w_ih_f    = (const float*)d_in[4];
    const float* w_hh_f    = (const float*)d_in[5];
    const float* b_f       = (const float*)d_in[6];
    const float* w_ih_b    = (const float*)d_in[7];
    const float* w_hh_b    = (const float*)d_in[8];
    const float* b_b       = (const float*)d_in[9];
    const float* lin_w     = (const float*)d_in[10];
    const float* lin_b     = (const float*)d_in[11];
    const float* trans     = (const float*)d_in[12];

    dim3 g1(SLEN / 16, 4, 2);
    k1_xg<<<g1, 256>>>(sent, embedding, w_ih_f, b_f, w_ih_b, b_b);
    k2_lstm<<<2 * CL, 256>>>(h0, c0, w_hh_f, w_hh_b);
    k3_feats<<<SLEN, 256>>>(lin_w, lin_b);

    cudaFuncSetAttribute(k4_viterbi, cudaFuncAttributeMaxDynamicSharedMemorySize,
                         SLEN * TAGS);
    k4_viterbi<<<1, 32, SLEN * TAGS>>>(trans, (float*)d_out, out_size);
}

// round 12
// speedup vs baseline: 1.1180x; 1.0238x over previous
#include <cuda_runtime.h>
#include <math.h>

#define SLEN 4096
#define EDIM 256
#define HDIM 256
#define TAGS 32
#define NEGV (-10000.0f)
#define CL 8            // CTAs per cluster (one cluster per direction)
#define STARTTAG 30
#define STOPTAG  31

// ---------------- scratch (device globals; no allocation allowed) ----------------
__device__ float g_xg[2][SLEN][4 * HDIM];           // 32 MB : precomputed input gates
__device__ __align__(16) float g_hs[2][SLEN][HDIM]; // 8 MB  : hidden states
__device__ float g_feats[SLEN][TAGS];               // 512 KB

// packed fp32x2 FMA (Blackwell FFMA2): d = a*b + c elementwise on float2
__device__ __forceinline__ float2 ffma2(float2 a, float2 b, float2 c) {
    float2 d;
    asm("fma.rn.f32x2 %0, %1, %2, %3;"
        : "=l"(*reinterpret_cast<unsigned long long*>(&d))
        : "l"(*reinterpret_cast<unsigned long long*>(&a)),
          "l"(*reinterpret_cast<unsigned long long*>(&b)),
          "l"(*reinterpret_cast<unsigned long long*>(&c)));
    return d;
}

// fast sigmoid/tanh via MUFU (__expf rel err ~1e-7: safe for argmax margins)
__device__ __forceinline__ float fast_sigmoid(float x) {
    float e = __expf(-x);
    return __fdividef(1.0f, 1.0f + e);
}
__device__ __forceinline__ float fast_tanh(float x) {
    float e = __expf(-2.0f * x);
    return __fdividef(1.0f - e, 1.0f + e);
}

// ---------------- K1: xg[d][t][r] = emb[sent_d(t)] . w_ih_d[r] + b_d[r] ----------
__global__ void k1_xg(const int* __restrict__ sent,
                      const float* __restrict__ embedding,
                      const float* __restrict__ w_ih_f, const float* __restrict__ b_f,
                      const float* __restrict__ w_ih_b, const float* __restrict__ b_b)
{
    __shared__ __align__(16) float embs[16][EDIM];
    const int d  = blockIdx.z;
    const int t0 = blockIdx.x * 16;
    const int n  = blockIdx.y * 256 + threadIdx.x;   // gate row 0..1023

    for (int tt = 0; tt < 16; tt++) {
        int pos  = t0 + tt;
        int spos = d ? (SLEN - 1 - pos) : pos;
        int tok  = sent[spos];
        embs[tt][threadIdx.x] = embedding[(size_t)tok * EDIM + threadIdx.x];
    }
    __syncthreads();

    const float* W = d ? w_ih_b : w_ih_f;
    const float* B = d ? b_b    : b_f;
    float2 acc[16];
    float bias = B[n];
#pragma unroll
    for (int tt = 0; tt < 16; tt++) acc[tt] = make_float2(bias, 0.0f);

    const float4* Wr = (const float4*)(W + (size_t)n * EDIM);
#pragma unroll 4
    for (int e4 = 0; e4 < EDIM / 4; e4++) {
        float4 w4 = __ldg(&Wr[e4]);
        float2 wA = make_float2(w4.x, w4.y);
        float2 wB = make_float2(w4.z, w4.w);
#pragma unroll
        for (int tt = 0; tt < 16; tt++) {
            float4 ev = *(const float4*)&embs[tt][e4 * 4];
            acc[tt] = ffma2(wA, make_float2(ev.x, ev.y), acc[tt]);
            acc[tt] = ffma2(wB, make_float2(ev.z, ev.w), acc[tt]);
        }
    }
#pragma unroll
    for (int tt = 0; tt < 16; tt++) g_xg[d][t0 + tt][n] = acc[tt].x + acc[tt].y;
}

// ---------------- K2: clustered bidirectional LSTM recurrence --------------------
// Grid = 16 CTAs = 2 clusters of 8 (one per direction), 256 thr/CTA.
// CTA rank owns j in [rank*32, rank*32+32). Warp w owns jl in [4w, 4w+4).
// Handshake: ZERO ordering ops; one st.async.v4.b32 per warp per target CTA
// carries mbarrier::complete_tx. Two alternating mbarriers, 4-deep h ring.
// Wait discipline: ONLY warp 0 does the acquire-trywait (one warp on the
// mbarrier word instead of eight); __syncthreads broadcasts completion and
// provides the ordering edge for the other warps' h reads.
__global__ void __launch_bounds__(256, 1) __cluster_dims__(CL, 1, 1)
k2_lstm(const float* __restrict__ h0, const float* __restrict__ c0,
        const float* __restrict__ w_hh_f, const float* __restrict__ w_hh_b)
{
    __shared__ __align__(16) float hbuf[4][HDIM];   // 4-deep h ring, filled via st.async
    __shared__ __align__(8) unsigned long long mbar[2];

    const int d = blockIdx.x >> 3;                  // cluster id = direction
    unsigned crank;
    asm("mov.u32 %0, %%cluster_ctarank;" : "=r"(crank));
    const int tid  = threadIdx.x;
    const int w    = tid >> 5;
    const int l    = tid & 31;
    const int a    = l >> 3;                        // j slot within warp
    const int gate = (l >> 1) & 3;                  // i,f,g,o
    const int half = l & 1;                         // column half (interleaved)
    const int jl   = w * 4 + a;                     // 0..31
    const int j    = (int)crank * 32 + jl;          // global h index
    const int j0   = (int)crank * 32 + w * 4;       // warp's first j
    const int grow = gate * HDIM + j;               // gate row in [0,1024)

    const float* W = d ? w_hh_b : w_hh_f;
    float4 wr[32];                                  // 128 weights / thread
#pragma unroll
    for (int m = 0; m < 32; m++)
        wr[m] = *(const float4*)(W + (size_t)grow * HDIM + (size_t)(m * 2 + half) * 4);

    unsigned hb = (unsigned)__cvta_generic_to_shared(&hbuf[0][0]);
    unsigned mb = (unsigned)__cvta_generic_to_shared(&mbar[0]);
    // per-lane scalar remote addresses: this lane's send target is CTA (l & 7)
    unsigned r_h, r_m;
    {
        unsigned myc = (unsigned)(l & 7);
        asm("mapa.shared::cluster.u32 %0, %1, %2;" : "=r"(r_h) : "r"(hb), "r"(myc));
        asm("mapa.shared::cluster.u32 %0, %1, %2;" : "=r"(r_m) : "r"(mb), "r"(myc));
    }

    if (tid == 0) {
        asm volatile("mbarrier.init.shared.b64 [%0], %1;" :: "r"(mb),     "r"(1) : "memory");
        asm volatile("mbarrier.init.shared.b64 [%0], %1;" :: "r"(mb + 8), "r"(1) : "memory");
        // pre-post: h_1 arrives on mbar[1], h_2 on mbar[0]; 1024 B each
        asm volatile("mbarrier.arrive.expect_tx.shared.b64 _, [%0], %1;"
                     :: "r"(mb + 8), "r"(HDIM * 4) : "memory");
        asm volatile("mbarrier.arrive.expect_tx.shared.b64 _, [%0], %1;"
                     :: "r"(mb),     "r"(HDIM * 4) : "memory");
    }
    hbuf[0][tid] = h0[d * HDIM + tid];              // step 1 reads hbuf[0] = h0
    __syncthreads();
    // all CTAs' mbarrier init done before any st.async can target them
    asm volatile("barrier.cluster.arrive.aligned;" ::: "memory");
    asm volatile("barrier.cluster.wait.aligned;"   ::: "memory");

    const bool prod = ((l & 7) == 0);               // lanes 0,8,16,24: own a j
    float cst = c0[d * HDIM + j];                   // used only on prod lanes

    for (int s = 1; s <= SLEN; s++) {
        const int t = s - 1;
        // xg prefetch: issued before the wait, overlaps the mbarrier sleep
        float xw = __ldg(&g_xg[d][t][grow]);

        if (s > 1) {                                // wait h_{s-1} on mbar[(s-1)&1]
            if (w == 0) {                           // ONE warp on the mbarrier word
                unsigned mbw = mb + (unsigned)((s - 1) & 1) * 8u;
                unsigned par = (unsigned)(((s - 2) >> 1) & 1);
                unsigned done;
                asm volatile(
                    "{\n\t.reg .pred p;\n\t"
                    "mbarrier.try_wait.parity.acquire.cluster.shared::cta.b64 p, [%1], %2, 0x989680;\n\t"
                    "selp.b32 %0, 1, 0, p;\n\t}"
                    : "=r"(done) : "r"(mbw), "r"(par) : "memory");
                while (!done) {
                    asm volatile(
                        "{\n\t.reg .pred p;\n\t"
                        "mbarrier.try_wait.parity.acquire.cluster.shared::cta.b64 p, [%1], %2, 0x989680;\n\t"
                        "selp.b32 %0, 1, 0, p;\n\t}"
                        : "=r"(done) : "r"(mbw), "r"(par) : "memory");
                }
                // this barrier's next phase handles h_{s+1}: re-arm it now
                if (l == 0 && s + 1 <= SLEN)
                    asm volatile("mbarrier.arrive.expect_tx.shared.b64 _, [%0], %1;"
                                 :: "r"(mbw), "r"(HDIM * 4) : "memory");
            }
            __syncthreads();                        // broadcast completion + ordering
        }

        const float* hsm = &hbuf[(s - 1) & 3][0];
        float2 acc[4];
#pragma unroll
        for (int k = 0; k < 4; k++) acc[k] = make_float2(0.0f, 0.0f);
#pragma unroll
        for (int m = 0; m < 32; m++) {
            float4 h4 = *(const float4*)(hsm + (m * 2 + half) * 4);
            float4 w4 = wr[m];
            float2 ac = acc[m & 3];
            ac = ffma2(make_float2(w4.x, w4.y), make_float2(h4.x, h4.y), ac);
            ac = ffma2(make_float2(w4.z, w4.w), make_float2(h4.z, h4.w), ac);
            acc[m & 3] = ac;
        }
        float accS = ((acc[0].x + acc[0].y) + (acc[1].x + acc[1].y))
                   + ((acc[2].x + acc[2].y) + (acc[3].x + acc[3].y));
        accS += __shfl_xor_sync(0xffffffffu, accS, 1);   // combine halves

        float av  = accS + xw;
        float val = (gate == 2) ? fast_tanh(av) : fast_sigmoid(av);

        const int base = l & 24;                    // lane group of this j
        float iv = __shfl_sync(0xffffffffu, val, base + 0);
        float fv = __shfl_sync(0xffffffffu, val, base + 2);
        float gv = __shfl_sync(0xffffffffu, val, base + 4);
        float ov = __shfl_sync(0xffffffffu, val, base + 6);

        float hv = 0.0f;
        if (prod) {
            cst = fmaf(fv, cst, iv * gv);
            hv  = ov * fast_tanh(cst);
        }
        // gather warp's 4 h-values to all lanes; lanes 0..7 send to CTA c = l
        float h0v = __shfl_sync(0xffffffffu, hv, 0);
        float h1v = __shfl_sync(0xffffffffu, hv, 8);
        float h2v = __shfl_sync(0xffffffffu, hv, 16);
        float h3v = __shfl_sync(0xffffffffu, hv, 24);

        if (l < CL) {
            unsigned dst  = r_h + (unsigned)(((s & 3) * HDIM + j0) * 4);
            unsigned mdst = r_m + (unsigned)((s & 1) * 8);
            asm volatile(
                "st.async.weak.shared::cluster.mbarrier::complete_tx::bytes.v4.b32 "
                "[%0], {%1, %2, %3, %4}, [%5];"
                :: "r"(dst),
                   "r"(__float_as_uint(h0v)), "r"(__float_as_uint(h1v)),
                   "r"(__float_as_uint(h2v)), "r"(__float_as_uint(h3v)),
                   "r"(mdst) : "memory");
        }
        if (l == 0)
            __stcg((float4*)&g_hs[d][t][j0], make_float4(h0v, h1v, h2v, h3v));
    }

    // no CTA may exit while peers still write into its SMEM
    asm volatile("barrier.cluster.arrive.aligned;" ::: "memory");
    asm volatile("barrier.cluster.wait.aligned;"   ::: "memory");
}

// ---------------- K3: feats[t] = [hs_f[t], hs_b[S-1-t]] @ lin_w^T + lin_b --------
__global__ void k3_feats(const float* __restrict__ lin_w, const float* __restrict__ lin_b)
{
    __shared__ __align__(16) float cat[2 * HDIM];
    const int t   = blockIdx.x;
    const int tid = threadIdx.x;                // 256
    cat[tid]        = g_hs[0][t][tid];
    cat[HDIM + tid] = g_hs[1][SLEN - 1 - t][tid];
    __syncthreads();

    const int n = tid >> 3, seg = tid & 7;
    const float* w  = lin_w + (size_t)n * 2 * HDIM + seg * 64;
    const float* cc = cat + seg * 64;
    float s = 0.0f;
#pragma unroll 16
    for (int k = 0; k < 64; k++) s = fmaf(w[k], cc[k], s);
    s += __shfl_xor_sync(0xffffffffu, s, 1);
    s += __shfl_xor_sync(0xffffffffu, s, 2);
    s += __shfl_xor_sync(0xffffffffu, s, 4);
    if (seg == 0) g_feats[t][n] = s + lin_b[n];
}

// ---------------- K4: single-warp Viterbi + backtrack (bps in SMEM) --------------
__global__ void __launch_bounds__(32, 1) k4_viterbi(
    const float* __restrict__ trans, float* __restrict__ out, int out_size)
{
    extern __shared__ unsigned char bps[];      // SLEN*TAGS bytes = 128 KB
    const int lane = threadIdx.x;

    float trn[TAGS];
#pragma unroll
    for (int p = 0; p < TAGS; p++) trn[p] = __ldg(&trans[lane * TAGS + p]);
    const float stop_tr = __ldg(&trans[STOPTAG * TAGS + lane]);

    float fv  = (lane == STARTTAG) ? 0.0f : NEGV;
    float ftc = g_feats[0][lane];
    float ftn = g_feats[1][lane];

    for (int t = 0; t < SLEN; t++) {
        float v[TAGS];
        int   bi[TAGS];
#pragma unroll
        for (int p = 0; p < TAGS; p++) {
            v[p]  = __shfl_sync(0xffffffffu, fv, p) + trn[p];
            bi[p] = p;
        }
        // first-max tree: strict > keeps the lower index on ties (== jnp.argmax)
#pragma unroll
        for (int s = 1; s < TAGS; s <<= 1) {
#pragma unroll
            for (int k = 0; k < TAGS; k += 2 * s) {
                if (v[k + s] > v[k]) { v[k] = v[k + s]; bi[k] = bi[k + s]; }
            }
        }
        bps[t * TAGS + lane] = (unsigned char)bi[0];
        fv  = v[0] + ftc;
        ftc = ftn;
        ftn = (t + 2 < SLEN) ? g_feats[t + 2][lane] : 0.0f;
    }

    float v = fv + stop_tr;
    int   b = lane;
#pragma unroll
    for (int ofs = 16; ofs > 0; ofs >>= 1) {
        float ov = __shfl_down_sync(0xffffffffu, v, ofs);
        int   oi = __shfl_down_sync(0xffffffffu, b, ofs);
        if (ov > v || (ov == v && oi < b)) { v = ov; b = oi; }
    }

    if (lane == 0) {
        const int off = (out_size > SLEN) ? 1 : 0;
        if (off) out[0] = v;
        int cur = b;
        for (int t = SLEN - 1; t >= 0; t--) {
            int idx = off + t;
            if (idx < out_size) out[idx] = (float)cur;
            cur = bps[t * TAGS + cur];
        }
    }
}

// ---------------- launch ----------------------------------------------------------
extern "C" void kernel_launch(void* const* d_in, const int* in_sizes, int n_in,
                              void* d_out, int out_size)
{
    (void)in_sizes; (void)n_in;
    const int*   sent      = (const int*)  d_in[0];
    const float* h0        = (const float*)d_in[1];
    const float* c0        = (const float*)d_in[2];
    const float* embedding = (const float*)d_in[3];
    const float* w_ih_f    = (const float*)d_in[4];
    const float* w_hh_f    = (const float*)d_in[5];
    const float* b_f       = (const float*)d_in[6];
    const float* w_ih_b    = (const float*)d_in[7];
    const float* w_hh_b    = (const float*)d_in[8];
    const float* b_b       = (const float*)d_in[9];
    const float* lin_w     = (const float*)d_in[10];
    const float* lin_b     = (const float*)d_in[11];
    const float* trans     = (const float*)d_in[12];

    dim3 g1(SLEN / 16, 4, 2);
    k1_xg<<<g1, 256>>>(sent, embedding, w_ih_f, b_f, w_ih_b, b_b);
    k2_lstm<<<2 * CL, 256>>>(h0, c0, w_hh_f, w_hh_b);
    k3_feats<<<SLEN, 256>>>(lin_w, lin_b);

    cudaFuncSetAttribute(k4_viterbi, cudaFuncAttributeMaxDynamicSharedMemorySize,
                         SLEN * TAGS);
    k4_viterbi<<<1, 32, SLEN * TAGS>>>(trans, (float*)d_out, out_size);
}